// round 9
// baseline (speedup 1.0000x reference)
#include <cuda_runtime.h>
#include <cuda_bf16.h>
#include <cstdint>

#define Bb  2
#define Ss  2048
#define Dd  1024
#define Hh  16
#define DKk 64
#define Mm  (Bb*Ss)

// ---------------- scratch (allocation-free: device globals) ----------------
__device__ __nv_bfloat16 g_A0hi[(size_t)Mm*Dd], g_A0lo[(size_t)Mm*Dd];
__device__ __nv_bfloat16 g_A1hi[(size_t)Mm*Dd], g_A1lo[(size_t)Mm*Dd];
__device__ __nv_bfloat16 g_A2hi[(size_t)Mm*Dd], g_A2lo[(size_t)Mm*Dd];
__device__ __nv_bfloat16 g_W0hi[(size_t)Dd*Dd], g_W0lo[(size_t)Dd*Dd];
__device__ __nv_bfloat16 g_W1hi[(size_t)Dd*Dd], g_W1lo[(size_t)Dd*Dd];
__device__ __nv_bfloat16 g_W2hi[(size_t)Dd*Dd], g_W2lo[(size_t)Dd*Dd];
__device__ __nv_bfloat16 g_W3hi[(size_t)Dd*Dd], g_W3lo[(size_t)Dd*Dd];
__device__ __nv_bfloat16 g_Qhi[(size_t)Bb*Hh*Ss*DKk], g_Qlo[(size_t)Bb*Hh*Ss*DKk];
__device__ __nv_bfloat16 g_Khi[(size_t)Bb*Hh*Ss*DKk], g_Klo[(size_t)Bb*Hh*Ss*DKk];
__device__ __nv_bfloat16 g_Vthi[(size_t)Bb*Hh*DKk*Ss], g_Vtlo[(size_t)Bb*Hh*DKk*Ss];
__device__ __nv_bfloat16 g_Xhi[(size_t)Mm*Dd], g_Xlo[(size_t)Mm*Dd];

// ---------------- helpers (arch-portable PTX) --------
__device__ __forceinline__ uint32_t smem_u32(const void* p) {
    uint32_t a;
    asm("{ .reg .u64 t; cvta.to.shared.u64 t, %1; cvt.u32.u64 %0, t; }"
        : "=r"(a) : "l"(p));
    return a;
}
__device__ __forceinline__ void ldsm4(uint32_t a, uint32_t& r0, uint32_t& r1,
                                      uint32_t& r2, uint32_t& r3) {
    asm volatile("ldmatrix.sync.aligned.m8n8.x4.shared.b16 {%0,%1,%2,%3}, [%4];"
                 : "=r"(r0), "=r"(r1), "=r"(r2), "=r"(r3) : "r"(a));
}
__device__ __forceinline__ void mma16816(float* c, uint32_t a0, uint32_t a1,
                                         uint32_t a2, uint32_t a3,
                                         uint32_t b0, uint32_t b1) {
    asm volatile(
        "mma.sync.aligned.m16n8k16.row.col.f32.bf16.bf16.f32 "
        "{%0,%1,%2,%3}, {%4,%5,%6,%7}, {%8,%9}, {%0,%1,%2,%3};"
        : "+f"(c[0]), "+f"(c[1]), "+f"(c[2]), "+f"(c[3])
        : "r"(a0), "r"(a1), "r"(a2), "r"(a3), "r"(b0), "r"(b1));
}
__device__ __forceinline__ uint32_t packbf(float lo, float hi) {
    uint32_t r;
    asm("cvt.rn.bf16x2.f32 %0, %1, %2;" : "=r"(r) : "f"(hi), "f"(lo));
    return r;
}
__device__ __forceinline__ float bflo_f(uint32_t p) { return __uint_as_float(p << 16); }
__device__ __forceinline__ float bfhi_f(uint32_t p) { return __uint_as_float(p & 0xffff0000u); }
__device__ __forceinline__ float ex2f(float x) {
    float r;
    asm("ex2.approx.f32 %0, %1;" : "=f"(r) : "f"(x));
    return r;
}

__device__ __forceinline__ void cpasync16(uint32_t saddr, const void* g) {
    asm volatile("cp.async.ca.shared.global [%0], [%1], 16;"
                 :: "r"(saddr), "l"(g) : "memory");
}
#define CP_COMMIT() asm volatile("cp.async.commit_group;" ::: "memory")
#define CP_WAIT0()  asm volatile("cp.async.wait_group 0;" ::: "memory")
#define CP_WAIT1()  asm volatile("cp.async.wait_group 1;" ::: "memory")

// ---------------------------------------------------------------------------
// merged fp32 -> bf16 hi/lo splits for q,k,v activations
// ---------------------------------------------------------------------------
__global__ __launch_bounds__(256) void conv_act_all(
    const float* __restrict__ q, const float* __restrict__ k,
    const float* __restrict__ v)
{
    const float* src = (blockIdx.y == 0) ? q : (blockIdx.y == 1) ? k : v;
    __nv_bfloat16* hi = (blockIdx.y == 0) ? g_A0hi : (blockIdx.y == 1) ? g_A1hi : g_A2hi;
    __nv_bfloat16* lo = (blockIdx.y == 0) ? g_A0lo : (blockIdx.y == 1) ? g_A1lo : g_A2lo;
    int i = blockIdx.x * blockDim.x + threadIdx.x;
    float4 vv = ((const float4*)src)[i];
    uint32_t h0 = packbf(vv.x, vv.y), h1 = packbf(vv.z, vv.w);
    ((uint32_t*)hi)[i * 2 + 0] = h0;
    ((uint32_t*)hi)[i * 2 + 1] = h1;
    ((uint32_t*)lo)[i * 2 + 0] = packbf(vv.x - bflo_f(h0), vv.y - bfhi_f(h0));
    ((uint32_t*)lo)[i * 2 + 1] = packbf(vv.z - bflo_f(h1), vv.w - bfhi_f(h1));
}

// ---------------------------------------------------------------------------
// merged weight transpose + split: W[K,N] -> WT[N,K] hi/lo, 4 weights
// ---------------------------------------------------------------------------
__global__ __launch_bounds__(256) void conv_wt_all(
    const float* __restrict__ w0, const float* __restrict__ w1,
    const float* __restrict__ w2, const float* __restrict__ w3)
{
    __shared__ float ts[32][33];
    const int z = blockIdx.z;
    const float* W = (z == 0) ? w0 : (z == 1) ? w1 : (z == 2) ? w2 : w3;
    __nv_bfloat16* hiT = (z == 0) ? g_W0hi : (z == 1) ? g_W1hi : (z == 2) ? g_W2hi : g_W3hi;
    __nv_bfloat16* loT = (z == 0) ? g_W0lo : (z == 1) ? g_W1lo : (z == 2) ? g_W2lo : g_W3lo;
    int tx = threadIdx.x, ty = threadIdx.y;          // 32 x 8
    int bn = blockIdx.x * 32, bk = blockIdx.y * 32;
    #pragma unroll
    for (int r = 0; r < 4; r++)
        ts[ty + r * 8][tx] = W[(size_t)(bk + ty + r * 8) * Dd + bn + tx];
    __syncthreads();
    #pragma unroll
    for (int r = 0; r < 4; r++) {
        float x = ts[tx][ty + r * 8];
        __nv_bfloat16 h = __float2bfloat16(x);
        size_t o = (size_t)(bn + ty + r * 8) * Dd + bk + tx;
        hiT[o] = h;
        loT[o] = __float2bfloat16(x - __bfloat162float(h));
    }
}

// ---------------------------------------------------------------------------
// HMMA bf16x3 GEMM body: 256x128 CTA tile, 3-stage cp.async, 1 CTA/SM.
// 8 warps as 4m x 2n, warp tile 64x64.
// mode 0: fp32 row-major; 1: bf16 hi/lo [B,H,S,DK]; 2: bf16 hi/lo [B,H,DK,S].
// ---------------------------------------------------------------------------
#define KCH   32
#define NCHUNK (Dd / KCH)              // 32
#define SROW  40                       // padded halves per row (80B)
#define AHI_OFF 0
#define ALO_OFF (256 * SROW * 2)       // 20480
#define WHI_OFF (2 * 256 * SROW * 2)   // 40960
#define WLO_OFF (WHI_OFF + 128 * SROW * 2)  // 51200
#define STAGEB  (WLO_OFF + 128 * SROW * 2)  // 61440
#define GSMEM   (3 * STAGEB)           // 184320

__device__ __forceinline__ void hgemm_body(
    const __nv_bfloat16* __restrict__ Ahi, const __nv_bfloat16* __restrict__ Alo,
    const __nv_bfloat16* __restrict__ Whi, const __nv_bfloat16* __restrict__ Wlo,
    const float* __restrict__ bias, float* __restrict__ Cf,
    __nv_bfloat16* __restrict__ Chi, __nv_bfloat16* __restrict__ Clo,
    int mode, __nv_bfloat16* sm)
{
    const int tid  = threadIdx.x;
    const int wid  = tid >> 5, lane = tid & 31;
    const int bm   = blockIdx.y * 256, bn = blockIdx.x * 128;
    const int wm   = wid & 3, wn = wid >> 2;

    float c[4][8][4];
    #pragma unroll
    for (int i = 0; i < 4; i++)
        #pragma unroll
        for (int j = 0; j < 8; j++)
            #pragma unroll
            for (int r = 0; r < 4; r++) c[i][j][r] = 0.f;

    const uint32_t sb = smem_u32(sm);
    // loader: thread t owns A row t (hi+lo, 4x16B each) and one W row
    const int ar = tid;
    const int wr = tid & 127;
    const __nv_bfloat16* Wsel = (tid < 128) ? Whi : Wlo;
    const uint32_t woff_sel = (tid < 128) ? (uint32_t)WHI_OFF : (uint32_t)WLO_OFF;

    #define ISSUE_CHUNK(cc, st) do {                                            \
        const uint32_t base = sb + (uint32_t)(st) * STAGEB;                     \
        const int k0_ = (cc) * KCH;                                             \
        const __nv_bfloat16* ah = &Ahi[(size_t)(bm + ar) * Dd + k0_];           \
        const __nv_bfloat16* al = &Alo[(size_t)(bm + ar) * Dd + k0_];           \
        const __nv_bfloat16* wp = &Wsel[(size_t)(bn + wr) * Dd + k0_];          \
        _Pragma("unroll")                                                       \
        for (int j_ = 0; j_ < 4; j_++) {                                        \
            cpasync16(base + AHI_OFF + (uint32_t)(ar * 80 + j_ * 16), ah + j_ * 8); \
            cpasync16(base + ALO_OFF + (uint32_t)(ar * 80 + j_ * 16), al + j_ * 8); \
        }                                                                       \
        _Pragma("unroll")                                                       \
        for (int j_ = 0; j_ < 4; j_++)                                          \
            cpasync16(base + woff_sel + (uint32_t)(wr * 80 + j_ * 16), wp + j_ * 8); \
        CP_COMMIT();                                                            \
    } while (0)

    const uint32_t aoff =
        (uint32_t)(((wm * 64 + (lane & 15)) * SROW + (lane >> 4) * 8) * 2);
    // B ldsm4: lanes 0-7 -> (n0,k0), 8-15 -> (n0,k8), 16-23 -> (n1,k0), 24-31 -> (n1,k8)
    const uint32_t boff =
        (uint32_t)(((wn * 64 + (lane >> 4) * 8 + (lane & 7)) * SROW
                    + ((lane >> 3) & 1) * 8) * 2);

    ISSUE_CHUNK(0, 0);
    ISSUE_CHUNK(1, 1);

    int st = 0, st2 = 2;
    for (int cc = 0; cc < NCHUNK; cc++) {
        if (cc + 1 < NCHUNK) { CP_WAIT1(); } else { CP_WAIT0(); }
        __syncthreads();
        if (cc + 2 < NCHUNK) ISSUE_CHUNK(cc + 2, st2);

        const uint32_t bufb = sb + (uint32_t)st * STAGEB;
        #pragma unroll
        for (int pass = 0; pass < 3; pass++) {
            const uint32_t Ab = bufb + aoff + (pass == 2 ? (uint32_t)ALO_OFF : (uint32_t)AHI_OFF);
            const uint32_t Wb = bufb + boff + (pass == 1 ? (uint32_t)WLO_OFF : (uint32_t)WHI_OFF);
            #pragma unroll
            for (int ks = 0; ks < 2; ks++) {
                uint32_t a[4][4], b[8][2];
                #pragma unroll
                for (int mi = 0; mi < 4; mi++)
                    ldsm4(Ab + mi * (16 * SROW * 2) + ks * 32,
                          a[mi][0], a[mi][1], a[mi][2], a[mi][3]);
                #pragma unroll
                for (int nb = 0; nb < 4; nb++)
                    ldsm4(Wb + nb * (16 * SROW * 2) + ks * 32,
                          b[2 * nb][0], b[2 * nb][1], b[2 * nb + 1][0], b[2 * nb + 1][1]);
                #pragma unroll
                for (int mi = 0; mi < 4; mi++)
                    #pragma unroll
                    for (int ni = 0; ni < 8; ni++)
                        mma16816(c[mi][ni], a[mi][0], a[mi][1], a[mi][2], a[mi][3],
                                 b[ni][0], b[ni][1]);
            }
        }
        st = (st == 2) ? 0 : st + 1;
        st2 = (st2 == 2) ? 0 : st2 + 1;
    }

    // ---- epilogue ----
    const int mrow0 = bm + wm * 64 + (lane >> 2);
    const int ncol0 = bn + wn * 64 + (lane & 3) * 2;
    #pragma unroll
    for (int mi = 0; mi < 4; mi++) {
        #pragma unroll
        for (int h2 = 0; h2 < 2; h2++) {
            const int m = mrow0 + mi * 16 + h2 * 8;
            const int b = m >> 11, s = m & 2047;
            #pragma unroll
            for (int ni = 0; ni < 8; ni++) {
                const int n = ncol0 + ni * 8;
                float v0 = c[mi][ni][h2 * 2 + 0] + bias[n];
                float v1 = c[mi][ni][h2 * 2 + 1] + bias[n + 1];
                if (mode == 0) {
                    float2 v; v.x = v0; v.y = v1;
                    *(float2*)&Cf[(size_t)m * Dd + n] = v;
                } else {
                    const int h = n >> 6, dk = n & 63;
                    uint32_t hp = packbf(v0, v1);
                    uint32_t lp = packbf(v0 - bflo_f(hp), v1 - bfhi_f(hp));
                    if (mode == 1) {
                        size_t o = (((size_t)(b * Hh + h)) * Ss + s) * DKk + dk;
                        *(uint32_t*)&Chi[o] = hp;
                        *(uint32_t*)&Clo[o] = lp;
                    } else {
                        size_t o = (((size_t)(b * Hh + h)) * DKk + dk) * Ss + s;
                        Chi[o]      = __ushort_as_bfloat16((uint16_t)(hp & 0xffff));
                        Chi[o + Ss] = __ushort_as_bfloat16((uint16_t)(hp >> 16));
                        Clo[o]      = __ushort_as_bfloat16((uint16_t)(lp & 0xffff));
                        Clo[o + Ss] = __ushort_as_bfloat16((uint16_t)(lp >> 16));
                    }
                }
            }
        }
    }
    #undef ISSUE_CHUNK
}

// batched QKV projections: blockIdx.z selects {Q, K, V}
__global__ __launch_bounds__(256, 1) void hgemm_qkv(
    const float* __restrict__ b_q, const float* __restrict__ b_k,
    const float* __restrict__ b_v)
{
    extern __shared__ __nv_bfloat16 smg[];
    const int z = blockIdx.z;
    if (z == 0)
        hgemm_body(g_A0hi, g_A0lo, g_W0hi, g_W0lo, b_q, nullptr, g_Qhi, g_Qlo, 1, smg);
    else if (z == 1)
        hgemm_body(g_A1hi, g_A1lo, g_W1hi, g_W1lo, b_k, nullptr, g_Khi, g_Klo, 1, smg);
    else
        hgemm_body(g_A2hi, g_A2lo, g_W2hi, g_W2lo, b_v, nullptr, g_Vthi, g_Vtlo, 2, smg);
}

__global__ __launch_bounds__(256, 1) void hgemm_out(
    const float* __restrict__ b_o, float* __restrict__ out)
{
    extern __shared__ __nv_bfloat16 smg[];
    hgemm_body(g_Xhi, g_Xlo, g_W3hi, g_W3lo, b_o, out, nullptr, nullptr, 0, smg);
}

// ---------------------------------------------------------------------------
// HMMA flash attention, bf16x3, causal, cp.async double-buffered KV.
// CTA: 64 query rows of one (b,h); 4 warps x 16 rows. KV tiles of 64 keys.
// ---------------------------------------------------------------------------
#define APAD 72
#define A_TILE (64 * APAD)             // 4608 halves = 9216 B
#define STAGE_H (4 * A_TILE)           // KH,KL,VH,VL per stage
#define ATTN_SMEM ((2 * A_TILE + 2 * STAGE_H) * 2)   // 92160 B
#define SCL2 0.18033688f               // 0.125 * log2(e)

__global__ __launch_bounds__(128, 1) void attn_mma_kernel(
    const __nv_bfloat16* __restrict__ Qhi, const __nv_bfloat16* __restrict__ Qlo,
    const __nv_bfloat16* __restrict__ Khi, const __nv_bfloat16* __restrict__ Klo,
    const __nv_bfloat16* __restrict__ Vthi, const __nv_bfloat16* __restrict__ Vtlo,
    __nv_bfloat16* __restrict__ Xhi, __nv_bfloat16* __restrict__ Xlo)
{
    extern __shared__ __nv_bfloat16 smA[];
    const int tid  = threadIdx.x;
    const int w    = tid >> 5, lane = tid & 31;
    const int bh   = blockIdx.y;
    const int iq   = gridDim.x - 1 - blockIdx.x;   // long CTAs first
    const size_t baseQK = (size_t)bh * Ss * DKk;
    const size_t baseV  = (size_t)bh * DKk * Ss;
    const uint32_t sb = smem_u32(smA);

    #define ISSUE_KV(j, stg) do {                                               \
        const __nv_bfloat16* Kh_g = Khi + baseQK + (size_t)(j) * 64 * DKk;      \
        const __nv_bfloat16* Kl_g = Klo + baseQK + (size_t)(j) * 64 * DKk;      \
        const __nv_bfloat16* Vh_g = Vthi + baseV + (size_t)(j) * 64;            \
        const __nv_bfloat16* Vl_g = Vtlo + baseV + (size_t)(j) * 64;            \
        const uint32_t st = sb + (uint32_t)((2 * A_TILE + (stg) * STAGE_H) * 2);\
        _Pragma("unroll")                                                       \
        for (int t = 0; t < 4; t++) {                                           \
            int idx = tid + t * 128;                                            \
            int row = idx >> 3, cu = (idx & 7) * 8;                             \
            cpasync16(st + (uint32_t)((0 * A_TILE + row * APAD + cu) * 2),      \
                      &Kh_g[row * DKk + cu]);                                   \
            cpasync16(st + (uint32_t)((1 * A_TILE + row * APAD + cu) * 2),      \
                      &Kl_g[row * DKk + cu]);                                   \
            cpasync16(st + (uint32_t)((2 * A_TILE + row * APAD + cu) * 2),      \
                      &Vh_g[(size_t)row * Ss + cu]);                            \
            cpasync16(st + (uint32_t)((3 * A_TILE + row * APAD + cu) * 2),      \
                      &Vl_g[(size_t)row * Ss + cu]);                            \
        }                                                                       \
        CP_COMMIT();                                                            \
    } while (0)

    // ---- load Q tile (64x64 hi/lo) + prefetch KV tile 0 ----
    {
        const __nv_bfloat16* Qh_g = Qhi + baseQK + (size_t)iq * 64 * DKk;
        const __nv_bfloat16* Ql_g = Qlo + baseQK + (size_t)iq * 64 * DKk;
        #pragma unroll
        for (int t = 0; t < 4; t++) {
            int idx = tid + t * 128;
            int row = idx >> 3, cu = (idx & 7) * 8;
            *(uint4*)&smA[0 * A_TILE + row * APAD + cu] = *(const uint4*)&Qh_g[row * DKk + cu];
            *(uint4*)&smA[1 * A_TILE + row * APAD + cu] = *(const uint4*)&Ql_g[row * DKk + cu];
        }
    }
    ISSUE_KV(0, 0);
    __syncthreads();

    const uint32_t a_off = (uint32_t)(((w * 16 + (lane & 15)) * APAD + (lane >> 4) * 8) * 2);
    const uint32_t b_off = (uint32_t)((((lane & 15)) * APAD + (lane >> 4) * 8) * 2);

    uint32_t qh[4][4], ql[4][4];
    #pragma unroll
    for (int kk = 0; kk < 4; kk++) {
        ldsm4(sb + 0 * A_TILE * 2 + a_off + kk * 32, qh[kk][0], qh[kk][1], qh[kk][2], qh[kk][3]);
        ldsm4(sb + 1 * A_TILE * 2 + a_off + kk * 32, ql[kk][0], ql[kk][1], ql[kk][2], ql[kk][3]);
    }

    float o[8][4];
    #pragma unroll
    for (int i = 0; i < 8; i++)
        #pragma unroll
        for (int r = 0; r < 4; r++) o[i][r] = 0.f;
    float m_lo = -1e30f, m_hi = -1e30f, l_lo = 0.f, l_hi = 0.f;

    for (int j = 0; j <= iq; j++) {
        CP_WAIT0();
        __syncthreads();
        if (j < iq) ISSUE_KV(j + 1, (j + 1) & 1);

        const uint32_t stb = sb + (uint32_t)((2 * A_TILE + (j & 1) * STAGE_H) * 2);

        // ---- scores S = Q K^T (3-term) ----
        float s[8][4];
        #pragma unroll
        for (int i = 0; i < 8; i++)
            #pragma unroll
            for (int r = 0; r < 4; r++) s[i][r] = 0.f;

        #pragma unroll
        for (int kk = 0; kk < 4; kk++) {
            uint32_t kh[8][2], kl[8][2];
            #pragma unroll
            for (int np = 0; np < 4; np++) {
                uint32_t t0, t1, t2, t3;
                ldsm4(stb + 0 * A_TILE * 2 + b_off + np * (16 * APAD * 2) + kk * 32, t0, t1, t2, t3);
                kh[2 * np][0] = t0; kh[2 * np][1] = t2;
                kh[2 * np + 1][0] = t1; kh[2 * np + 1][1] = t3;
                ldsm4(stb + 1 * A_TILE * 2 + b_off + np * (16 * APAD * 2) + kk * 32, t0, t1, t2, t3);
                kl[2 * np][0] = t0; kl[2 * np][1] = t2;
                kl[2 * np + 1][0] = t1; kl[2 * np + 1][1] = t3;
            }
            #pragma unroll
            for (int ni = 0; ni < 8; ni++)
                mma16816(s[ni], qh[kk][0], qh[kk][1], qh[kk][2], qh[kk][3],
                         kh[ni][0], kh[ni][1]);
            #pragma unroll
            for (int ni = 0; ni < 8; ni++)
                mma16816(s[ni], qh[kk][0], qh[kk][1], qh[kk][2], qh[kk][3],
                         kl[ni][0], kl[ni][1]);
            #pragma unroll
            for (int ni = 0; ni < 8; ni++)
                mma16816(s[ni], ql[kk][0], ql[kk][1], ql[kk][2], ql[kk][3],
                         kh[ni][0], kh[ni][1]);
        }

        // ---- scale into exp2 domain + causal mask (diagonal tile only) ----
        #pragma unroll
        for (int ni = 0; ni < 8; ni++)
            #pragma unroll
            for (int r = 0; r < 4; r++) s[ni][r] *= SCL2;
        if (j == iq) {
            const int rlo = w * 16 + (lane >> 2), rhi = rlo + 8;
            #pragma unroll
            for (int ni = 0; ni < 8; ni++) {
                const int c0 = ni * 8 + (lane & 3) * 2;
                if (c0 > rlo)     s[ni][0] = -1e30f;
                if (c0 + 1 > rlo) s[ni][1] = -1e30f;
                if (c0 > rhi)     s[ni][2] = -1e30f;
                if (c0 + 1 > rhi) s[ni][3] = -1e30f;
            }
        }

        // ---- online softmax (fp32, base-2) ----
        float mx_lo = s[0][0], mx_hi = s[0][2];
        #pragma unroll
        for (int ni = 0; ni < 8; ni++) {
            mx_lo = fmaxf(mx_lo, fmaxf(s[ni][0], s[ni][1]));
            mx_hi = fmaxf(mx_hi, fmaxf(s[ni][2], s[ni][3]));
        }
        mx_lo = fmaxf(mx_lo, __shfl_xor_sync(0xffffffffu, mx_lo, 1));
        mx_lo = fmaxf(mx_lo, __shfl_xor_sync(0xffffffffu, mx_lo, 2));
        mx_hi = fmaxf(mx_hi, __shfl_xor_sync(0xffffffffu, mx_hi, 1));
        mx_hi = fmaxf(mx_hi, __shfl_xor_sync(0xffffffffu, mx_hi, 2));
        const float mn_lo = fmaxf(m_lo, mx_lo), mn_hi = fmaxf(m_hi, mx_hi);
        const float al_lo = ex2f(m_lo - mn_lo), al_hi = ex2f(m_hi - mn_hi);

        uint32_t ph[8][2], pl[8][2];
        float sum_lo = 0.f, sum_hi = 0.f;
        #pragma unroll
        for (int ni = 0; ni < 8; ni++) {
            float p0 = ex2f(s[ni][0] - mn_lo);
            float p1 = ex2f(s[ni][1] - mn_lo);
            float p2 = ex2f(s[ni][2] - mn_hi);
            float p3 = ex2f(s[ni][3] - mn_hi);
            sum_lo += p0 + p1; sum_hi += p2 + p3;
            uint32_t h01 = packbf(p0, p1), h23 = packbf(p2, p3);
            ph[ni][0] = h01; ph[ni][1] = h23;
            pl[ni][0] = packbf(p0 - bflo_f(h01), p1 - bfhi_f(h01));
            pl[ni][1] = packbf(p2 - bflo_f(h23), p3 - bfhi_f(h23));
        }
        sum_lo += __shfl_xor_sync(0xffffffffu, sum_lo, 1);
        sum_lo += __shfl_xor_sync(0xffffffffu, sum_lo, 2);
        sum_hi += __shfl_xor_sync(0xffffffffu, sum_hi, 1);
        sum_hi += __shfl_xor_sync(0xffffffffu, sum_hi, 2);
        l_lo = l_lo * al_lo + sum_lo;  m_lo = mn_lo;
        l_hi = l_hi * al_hi + sum_hi;  m_hi = mn_hi;
        #pragma unroll
        for (int ni = 0; ni < 8; ni++) {
            o[ni][0] *= al_lo; o[ni][1] *= al_lo;
            o[ni][2] *= al_hi; o[ni][3] *= al_hi;
        }

        // ---- O += P V (3-term) ----
        #pragma unroll
        for (int kk = 0; kk < 4; kk++) {
            uint32_t vh[8][2], vl[8][2];
            #pragma unroll
            for (int np = 0; np < 4; np++) {
                uint32_t t0, t1, t2, t3;
                ldsm4(stb + 2 * A_TILE * 2 + b_off + np * (16 * APAD * 2) + kk * 32, t0, t1, t2, t3);
                vh[2 * np][0] = t0; vh[2 * np][1] = t2;
                vh[2 * np + 1][0] = t1; vh[2 * np + 1][1] = t3;
                ldsm4(stb + 3 * A_TILE * 2 + b_off + np * (16 * APAD * 2) + kk * 32, t0, t1, t2, t3);
                vl[2 * np][0] = t0; vl[2 * np][1] = t2;
                vl[2 * np + 1][0] = t1; vl[2 * np + 1][1] = t3;
            }
            const uint32_t pa0 = ph[2 * kk][0], pa1 = ph[2 * kk][1];
            const uint32_t pa2 = ph[2 * kk + 1][0], pa3 = ph[2 * kk + 1][1];
            const uint32_t qa0 = pl[2 * kk][0], qa1 = pl[2 * kk][1];
            const uint32_t qa2 = pl[2 * kk + 1][0], qa3 = pl[2 * kk + 1][1];
            #pragma unroll
            for (int ni = 0; ni < 8; ni++)
                mma16816(o[ni], pa0, pa1, pa2, pa3, vh[ni][0], vh[ni][1]);
            #pragma unroll
            for (int ni = 0; ni < 8; ni++)
                mma16816(o[ni], pa0, pa1, pa2, pa3, vl[ni][0], vl[ni][1]);
            #pragma unroll
            for (int ni = 0; ni < 8; ni++)
                mma16816(o[ni], qa0, qa1, qa2, qa3, vh[ni][0], vh[ni][1]);
        }
    }

    // ---- epilogue: X[b, s, h*64+dk] as bf16 hi/lo ----
    const float inv_lo = 1.f / l_lo, inv_hi = 1.f / l_hi;
    const int b = bh >> 4, h = bh & 15;
    const int s_lo = iq * 64 + w * 16 + (lane >> 2);
    const int s_hi = s_lo + 8;
    #pragma unroll
    for (int ni = 0; ni < 8; ni++) {
        const int dk = ni * 8 + (lane & 3) * 2;
        const size_t o_lo = ((size_t)(b * Ss + s_lo)) * Dd + h * DKk + dk;
        const size_t o_hi = ((size_t)(b * Ss + s_hi)) * Dd + h * DKk + dk;
        float v0 = o[ni][0] * inv_lo, v1 = o[ni][1] * inv_lo;
        float v2 = o[ni][2] * inv_hi, v3 = o[ni][3] * inv_hi;
        uint32_t hp0 = packbf(v0, v1), hp1 = packbf(v2, v3);
        *(uint32_t*)&Xhi[o_lo] = hp0;
        *(uint32_t*)&Xhi[o_hi] = hp1;
        *(uint32_t*)&Xlo[o_lo] = packbf(v0 - bflo_f(hp0), v1 - bfhi_f(hp0));
        *(uint32_t*)&Xlo[o_hi] = packbf(v2 - bflo_f(hp1), v3 - bfhi_f(hp1));
    }
    #undef ISSUE_KV
}

// ---------------------------------------------------------------------------
extern "C" void kernel_launch(void* const* d_in, const int* in_sizes, int n_in,
                              void* d_out, int out_size)
{
    const float* q   = (const float*)d_in[0];
    const float* k   = (const float*)d_in[1];
    const float* v   = (const float*)d_in[2];
    // d_in[3] = causal mask (int32) — causality computed analytically
    const float* w_q = (const float*)d_in[4];
    const float* b_q = (const float*)d_in[5];
    const float* w_k = (const float*)d_in[6];
    const float* b_k = (const float*)d_in[7];
    const float* w_v = (const float*)d_in[8];
    const float* b_v = (const float*)d_in[9];
    const float* w_o = (const float*)d_in[10];
    const float* b_o = (const float*)d_in[11];
    float* out = (float*)d_out;

    __nv_bfloat16 *pQh, *pQl, *pKh, *pKl, *pVh, *pVl, *pXh, *pXl;
    cudaGetSymbolAddress((void**)&pQh, g_Qhi);
    cudaGetSymbolAddress((void**)&pQl, g_Qlo);
    cudaGetSymbolAddress((void**)&pKh, g_Khi);
    cudaGetSymbolAddress((void**)&pKl, g_Klo);
    cudaGetSymbolAddress((void**)&pVh, g_Vthi);
    cudaGetSymbolAddress((void**)&pVl, g_Vtlo);
    cudaGetSymbolAddress((void**)&pXh, g_Xhi);
    cudaGetSymbolAddress((void**)&pXl, g_Xlo);

    cudaFuncSetAttribute(hgemm_qkv,
                         cudaFuncAttributeMaxDynamicSharedMemorySize, GSMEM);
    cudaFuncSetAttribute(hgemm_out,
                         cudaFuncAttributeMaxDynamicSharedMemorySize, GSMEM);
    cudaFuncSetAttribute(attn_mma_kernel,
                         cudaFuncAttributeMaxDynamicSharedMemorySize, ATTN_SMEM);

    // conversions (weights + activations)
    dim3 wt_grid(32, 32, 4), wt_block(32, 8);
    conv_wt_all<<<wt_grid, wt_block>>>(w_q, w_k, w_v, w_o);
    dim3 ca_grid(4096, 3);
    conv_act_all<<<ca_grid, 256>>>(q, k, v);

    // batched QKV projections (256x128 tiles)
    dim3 gemm_grid(Dd / 128, Mm / 256, 3);             // (8, 16, 3)
    hgemm_qkv<<<gemm_grid, 256, GSMEM>>>(b_q, b_k, b_v);

    // attention
    dim3 agrid(Ss / 64, Bb * Hh);                      // (32, 32)
    attn_mma_kernel<<<agrid, 128, ATTN_SMEM>>>(pQh, pQl, pKh, pKl, pVh, pVl, pXh, pXl);

    // output projection
    dim3 gemm_grid1(Dd / 128, Mm / 256, 1);            // (8, 16)
    hgemm_out<<<gemm_grid1, 256, GSMEM>>>(b_o, out);
}

// round 10
// speedup vs baseline: 1.3297x; 1.3297x over previous
#include <cuda_runtime.h>
#include <cuda_bf16.h>
#include <cstdint>

#define Bb  2
#define Ss  2048
#define Dd  1024
#define Hh  16
#define DKk 64
#define Mm  (Bb*Ss)

// ---------------- scratch (allocation-free: device globals) ----------------
__device__ __nv_bfloat16 g_A0hi[(size_t)Mm*Dd], g_A0lo[(size_t)Mm*Dd];
__device__ __nv_bfloat16 g_A1hi[(size_t)Mm*Dd], g_A1lo[(size_t)Mm*Dd];
__device__ __nv_bfloat16 g_A2hi[(size_t)Mm*Dd], g_A2lo[(size_t)Mm*Dd];
__device__ __nv_bfloat16 g_W0hi[(size_t)Dd*Dd], g_W0lo[(size_t)Dd*Dd];
__device__ __nv_bfloat16 g_W1hi[(size_t)Dd*Dd], g_W1lo[(size_t)Dd*Dd];
__device__ __nv_bfloat16 g_W2hi[(size_t)Dd*Dd], g_W2lo[(size_t)Dd*Dd];
__device__ __nv_bfloat16 g_W3hi[(size_t)Dd*Dd], g_W3lo[(size_t)Dd*Dd];
__device__ __nv_bfloat16 g_Qhi[(size_t)Bb*Hh*Ss*DKk], g_Qlo[(size_t)Bb*Hh*Ss*DKk];
__device__ __nv_bfloat16 g_Khi[(size_t)Bb*Hh*Ss*DKk], g_Klo[(size_t)Bb*Hh*Ss*DKk];
__device__ __nv_bfloat16 g_Vthi[(size_t)Bb*Hh*DKk*Ss], g_Vtlo[(size_t)Bb*Hh*DKk*Ss];
__device__ __nv_bfloat16 g_Xhi[(size_t)Mm*Dd], g_Xlo[(size_t)Mm*Dd];

// ---------------- helpers (arch-portable PTX) --------
__device__ __forceinline__ uint32_t smem_u32(const void* p) {
    uint32_t a;
    asm("{ .reg .u64 t; cvta.to.shared.u64 t, %1; cvt.u32.u64 %0, t; }"
        : "=r"(a) : "l"(p));
    return a;
}
__device__ __forceinline__ void ldsm4(uint32_t a, uint32_t& r0, uint32_t& r1,
                                      uint32_t& r2, uint32_t& r3) {
    asm volatile("ldmatrix.sync.aligned.m8n8.x4.shared.b16 {%0,%1,%2,%3}, [%4];"
                 : "=r"(r0), "=r"(r1), "=r"(r2), "=r"(r3) : "r"(a));
}
__device__ __forceinline__ void mma16816(float* c, uint32_t a0, uint32_t a1,
                                         uint32_t a2, uint32_t a3,
                                         uint32_t b0, uint32_t b1) {
    asm volatile(
        "mma.sync.aligned.m16n8k16.row.col.f32.bf16.bf16.f32 "
        "{%0,%1,%2,%3}, {%4,%5,%6,%7}, {%8,%9}, {%0,%1,%2,%3};"
        : "+f"(c[0]), "+f"(c[1]), "+f"(c[2]), "+f"(c[3])
        : "r"(a0), "r"(a1), "r"(a2), "r"(a3), "r"(b0), "r"(b1));
}
__device__ __forceinline__ uint32_t packbf(float lo, float hi) {
    uint32_t r;
    asm("cvt.rn.bf16x2.f32 %0, %1, %2;" : "=r"(r) : "f"(hi), "f"(lo));
    return r;
}
__device__ __forceinline__ float bflo_f(uint32_t p) { return __uint_as_float(p << 16); }
__device__ __forceinline__ float bfhi_f(uint32_t p) { return __uint_as_float(p & 0xffff0000u); }
__device__ __forceinline__ float ex2f(float x) {
    float r;
    asm("ex2.approx.f32 %0, %1;" : "=f"(r) : "f"(x));
    return r;
}

__device__ __forceinline__ void cpasync16(uint32_t saddr, const void* g) {
    asm volatile("cp.async.ca.shared.global [%0], [%1], 16;"
                 :: "r"(saddr), "l"(g) : "memory");
}
#define CP_COMMIT() asm volatile("cp.async.commit_group;" ::: "memory")
#define CP_WAIT0()  asm volatile("cp.async.wait_group 0;" ::: "memory")

// ---------------------------------------------------------------------------
// merged fp32 -> bf16 hi/lo splits for q,k,v activations
// ---------------------------------------------------------------------------
__global__ __launch_bounds__(256) void conv_act_all(
    const float* __restrict__ q, const float* __restrict__ k,
    const float* __restrict__ v)
{
    const float* src = (blockIdx.y == 0) ? q : (blockIdx.y == 1) ? k : v;
    __nv_bfloat16* hi = (blockIdx.y == 0) ? g_A0hi : (blockIdx.y == 1) ? g_A1hi : g_A2hi;
    __nv_bfloat16* lo = (blockIdx.y == 0) ? g_A0lo : (blockIdx.y == 1) ? g_A1lo : g_A2lo;
    int i = blockIdx.x * blockDim.x + threadIdx.x;
    float4 vv = ((const float4*)src)[i];
    uint32_t h0 = packbf(vv.x, vv.y), h1 = packbf(vv.z, vv.w);
    ((uint32_t*)hi)[i * 2 + 0] = h0;
    ((uint32_t*)hi)[i * 2 + 1] = h1;
    ((uint32_t*)lo)[i * 2 + 0] = packbf(vv.x - bflo_f(h0), vv.y - bfhi_f(h0));
    ((uint32_t*)lo)[i * 2 + 1] = packbf(vv.z - bflo_f(h1), vv.w - bfhi_f(h1));
}

// ---------------------------------------------------------------------------
// merged weight transpose + split: W[K,N] -> WT[N,K] hi/lo, 4 weights
// ---------------------------------------------------------------------------
__global__ __launch_bounds__(256) void conv_wt_all(
    const float* __restrict__ w0, const float* __restrict__ w1,
    const float* __restrict__ w2, const float* __restrict__ w3)
{
    __shared__ float ts[32][33];
    const int z = blockIdx.z;
    const float* W = (z == 0) ? w0 : (z == 1) ? w1 : (z == 2) ? w2 : w3;
    __nv_bfloat16* hiT = (z == 0) ? g_W0hi : (z == 1) ? g_W1hi : (z == 2) ? g_W2hi : g_W3hi;
    __nv_bfloat16* loT = (z == 0) ? g_W0lo : (z == 1) ? g_W1lo : (z == 2) ? g_W2lo : g_W3lo;
    int tx = threadIdx.x, ty = threadIdx.y;          // 32 x 8
    int bn = blockIdx.x * 32, bk = blockIdx.y * 32;
    #pragma unroll
    for (int r = 0; r < 4; r++)
        ts[ty + r * 8][tx] = W[(size_t)(bk + ty + r * 8) * Dd + bn + tx];
    __syncthreads();
    #pragma unroll
    for (int r = 0; r < 4; r++) {
        float x = ts[tx][ty + r * 8];
        __nv_bfloat16 h = __float2bfloat16(x);
        size_t o = (size_t)(bn + ty + r * 8) * Dd + bk + tx;
        hiT[o] = h;
        loT[o] = __float2bfloat16(x - __bfloat162float(h));
    }
}

// ---------------------------------------------------------------------------
// HMMA bf16x3 GEMM body: cp.async double-buffered, 2 CTAs/SM. (R7 config)
// CTA 128x128, K-chunk 32, 8 warps (2m x 4n), warp tile 64x32.
// mode 0: fp32 row-major; 1: bf16 hi/lo [B,H,S,DK]; 2: bf16 hi/lo [B,H,DK,S].
// ---------------------------------------------------------------------------
#define KCH   32
#define NCHUNK (Dd / KCH)          // 32
#define SROW  40                   // padded halves per row
#define ABYTES (128 * SROW * 2)    // 10240 B per array
#define BUFB  (4 * ABYTES)         // 40960 B per stage
#define GSMEM (2 * BUFB)           // 81920 B

__device__ __forceinline__ void hgemm_body(
    const __nv_bfloat16* __restrict__ Ahi, const __nv_bfloat16* __restrict__ Alo,
    const __nv_bfloat16* __restrict__ Whi, const __nv_bfloat16* __restrict__ Wlo,
    const float* __restrict__ bias, float* __restrict__ Cf,
    __nv_bfloat16* __restrict__ Chi, __nv_bfloat16* __restrict__ Clo,
    int mode, __nv_bfloat16* sm)
{
    const int tid  = threadIdx.x;
    const int wid  = tid >> 5, lane = tid & 31;
    const int bm   = blockIdx.y * 128, bn = blockIdx.x * 128;
    const int wm   = wid & 1, wn = wid >> 1;

    float c[4][4][4];
    #pragma unroll
    for (int i = 0; i < 4; i++)
        #pragma unroll
        for (int j = 0; j < 4; j++)
            #pragma unroll
            for (int r = 0; r < 4; r++) c[i][j][r] = 0.f;

    const int r0 = tid >> 2,         q0 = (tid & 3) * 8;
    const int r1 = (tid + 256) >> 2, q1 = ((tid + 256) & 3) * 8;
    const uint32_t sb = smem_u32(sm);

    #define ISSUE_CHUNK(cc, base) do {                                          \
        const int k0_ = (cc) * KCH;                                             \
        cpasync16((base) + (uint32_t)((0 * 128 * SROW + r0 * SROW + q0) * 2),   \
                  &Ahi[(size_t)(bm + r0) * Dd + k0_ + q0]);                     \
        cpasync16((base) + (uint32_t)((0 * 128 * SROW + r1 * SROW + q1) * 2),   \
                  &Ahi[(size_t)(bm + r1) * Dd + k0_ + q1]);                     \
        cpasync16((base) + (uint32_t)((1 * 128 * SROW + r0 * SROW + q0) * 2),   \
                  &Alo[(size_t)(bm + r0) * Dd + k0_ + q0]);                     \
        cpasync16((base) + (uint32_t)((1 * 128 * SROW + r1 * SROW + q1) * 2),   \
                  &Alo[(size_t)(bm + r1) * Dd + k0_ + q1]);                     \
        cpasync16((base) + (uint32_t)((2 * 128 * SROW + r0 * SROW + q0) * 2),   \
                  &Whi[(size_t)(bn + r0) * Dd + k0_ + q0]);                     \
        cpasync16((base) + (uint32_t)((2 * 128 * SROW + r1 * SROW + q1) * 2),   \
                  &Whi[(size_t)(bn + r1) * Dd + k0_ + q1]);                     \
        cpasync16((base) + (uint32_t)((3 * 128 * SROW + r0 * SROW + q0) * 2),   \
                  &Wlo[(size_t)(bn + r0) * Dd + k0_ + q0]);                     \
        cpasync16((base) + (uint32_t)((3 * 128 * SROW + r1 * SROW + q1) * 2),   \
                  &Wlo[(size_t)(bn + r1) * Dd + k0_ + q1]);                     \
        CP_COMMIT();                                                            \
    } while (0)

    const uint32_t aoff =
        (uint32_t)(((wm * 64 + (lane & 15)) * SROW + (lane >> 4) * 8) * 2);
    // B ldsm4: lanes 0-7 -> (n0,k0), 8-15 -> (n0,k8), 16-23 -> (n1,k0), 24-31 -> (n1,k8)
    const uint32_t boff4 =
        (uint32_t)(((wn * 32 + (lane >> 4) * 8 + (lane & 7)) * SROW
                    + ((lane >> 3) & 1) * 8) * 2);

    ISSUE_CHUNK(0, sb);

    for (int cc = 0; cc < NCHUNK; cc++) {
        CP_WAIT0();
        __syncthreads();
        if (cc + 1 < NCHUNK)
            ISSUE_CHUNK(cc + 1, sb + (uint32_t)((cc + 1) & 1) * BUFB);

        const uint32_t bufb = sb + (uint32_t)(cc & 1) * BUFB;
        #pragma unroll
        for (int pass = 0; pass < 3; pass++) {
            const uint32_t Ab  = bufb + aoff + (pass == 2 ? (uint32_t)ABYTES : 0u);
            const uint32_t Bbp = bufb + boff4 + 2u * ABYTES + (pass == 1 ? (uint32_t)ABYTES : 0u);
            #pragma unroll
            for (int ks = 0; ks < 2; ks++) {
                uint32_t a[4][4], b[4][2];
                #pragma unroll
                for (int mi = 0; mi < 4; mi++)
                    ldsm4(Ab + mi * (16 * SROW * 2) + ks * 32,
                          a[mi][0], a[mi][1], a[mi][2], a[mi][3]);
                #pragma unroll
                for (int nb = 0; nb < 2; nb++)
                    ldsm4(Bbp + nb * (16 * SROW * 2) + ks * 32,
                          b[2 * nb][0], b[2 * nb][1], b[2 * nb + 1][0], b[2 * nb + 1][1]);
                #pragma unroll
                for (int mi = 0; mi < 4; mi++)
                    #pragma unroll
                    for (int ni = 0; ni < 4; ni++)
                        mma16816(c[mi][ni], a[mi][0], a[mi][1], a[mi][2], a[mi][3],
                                 b[ni][0], b[ni][1]);
            }
        }
    }

    // ---- epilogue ----
    const int mrow0 = bm + wm * 64 + (lane >> 2);
    const int ncol0 = bn + wn * 32 + (lane & 3) * 2;
    #pragma unroll
    for (int mi = 0; mi < 4; mi++) {
        #pragma unroll
        for (int h2 = 0; h2 < 2; h2++) {
            const int m = mrow0 + mi * 16 + h2 * 8;
            const int b = m >> 11, s = m & 2047;
            #pragma unroll
            for (int ni = 0; ni < 4; ni++) {
                const int n = ncol0 + ni * 8;
                float v0 = c[mi][ni][h2 * 2 + 0] + bias[n];
                float v1 = c[mi][ni][h2 * 2 + 1] + bias[n + 1];
                if (mode == 0) {
                    float2 v; v.x = v0; v.y = v1;
                    *(float2*)&Cf[(size_t)m * Dd + n] = v;
                } else {
                    const int h = n >> 6, dk = n & 63;
                    uint32_t hp = packbf(v0, v1);
                    uint32_t lp = packbf(v0 - bflo_f(hp), v1 - bfhi_f(hp));
                    if (mode == 1) {
                        size_t o = (((size_t)(b * Hh + h)) * Ss + s) * DKk + dk;
                        *(uint32_t*)&Chi[o] = hp;
                        *(uint32_t*)&Clo[o] = lp;
                    } else {
                        size_t o = (((size_t)(b * Hh + h)) * DKk + dk) * Ss + s;
                        Chi[o]      = __ushort_as_bfloat16((uint16_t)(hp & 0xffff));
                        Chi[o + Ss] = __ushort_as_bfloat16((uint16_t)(hp >> 16));
                        Clo[o]      = __ushort_as_bfloat16((uint16_t)(lp & 0xffff));
                        Clo[o + Ss] = __ushort_as_bfloat16((uint16_t)(lp >> 16));
                    }
                }
            }
        }
    }
    #undef ISSUE_CHUNK
}

// batched QKV projections: blockIdx.z selects {Q, K, V}
__global__ __launch_bounds__(256, 2) void hgemm_qkv(
    const float* __restrict__ b_q, const float* __restrict__ b_k,
    const float* __restrict__ b_v)
{
    extern __shared__ __nv_bfloat16 smg[];
    const int z = blockIdx.z;
    if (z == 0)
        hgemm_body(g_A0hi, g_A0lo, g_W0hi, g_W0lo, b_q, nullptr, g_Qhi, g_Qlo, 1, smg);
    else if (z == 1)
        hgemm_body(g_A1hi, g_A1lo, g_W1hi, g_W1lo, b_k, nullptr, g_Khi, g_Klo, 1, smg);
    else
        hgemm_body(g_A2hi, g_A2lo, g_W2hi, g_W2lo, b_v, nullptr, g_Vthi, g_Vtlo, 2, smg);
}

__global__ __launch_bounds__(256, 2) void hgemm_out(
    const float* __restrict__ b_o, float* __restrict__ out)
{
    extern __shared__ __nv_bfloat16 smg[];
    hgemm_body(g_Xhi, g_Xlo, g_W3hi, g_W3lo, b_o, out, nullptr, nullptr, 0, smg);
}

// ---------------------------------------------------------------------------
// HMMA flash attention, bf16x3, causal, cp.async double-buffered KV.
// CTA: 64 query rows of one (b,h); 4 warps x 16 rows. KV tiles of 64 keys.
// exp/pack fused into the PV loop; sum-reduce deferred past the MMAs.
// ---------------------------------------------------------------------------
#define APAD 72
#define A_TILE (64 * APAD)             // 4608 halves = 9216 B
#define STAGE_H (4 * A_TILE)           // KH,KL,VH,VL per stage
#define ATTN_SMEM ((2 * A_TILE + 2 * STAGE_H) * 2)   // 92160 B
#define SCL2 0.18033688f               // 0.125 * log2(e)

__global__ __launch_bounds__(128, 1) void attn_mma_kernel(
    const __nv_bfloat16* __restrict__ Qhi, const __nv_bfloat16* __restrict__ Qlo,
    const __nv_bfloat16* __restrict__ Khi, const __nv_bfloat16* __restrict__ Klo,
    const __nv_bfloat16* __restrict__ Vthi, const __nv_bfloat16* __restrict__ Vtlo,
    __nv_bfloat16* __restrict__ Xhi, __nv_bfloat16* __restrict__ Xlo)
{
    extern __shared__ __nv_bfloat16 smA[];
    const int tid  = threadIdx.x;
    const int w    = tid >> 5, lane = tid & 31;
    const int bh   = blockIdx.y;
    const int iq   = gridDim.x - 1 - blockIdx.x;   // long CTAs first
    const size_t baseQK = (size_t)bh * Ss * DKk;
    const size_t baseV  = (size_t)bh * DKk * Ss;
    const uint32_t sb = smem_u32(smA);

    #define ISSUE_KV(j, stg) do {                                               \
        const __nv_bfloat16* Kh_g = Khi + baseQK + (size_t)(j) * 64 * DKk;      \
        const __nv_bfloat16* Kl_g = Klo + baseQK + (size_t)(j) * 64 * DKk;      \
        const __nv_bfloat16* Vh_g = Vthi + baseV + (size_t)(j) * 64;            \
        const __nv_bfloat16* Vl_g = Vtlo + baseV + (size_t)(j) * 64;            \
        const uint32_t st = sb + (uint32_t)((2 * A_TILE + (stg) * STAGE_H) * 2);\
        _Pragma("unroll")                                                       \
        for (int t = 0; t < 4; t++) {                                           \
            int idx = tid + t * 128;                                            \
            int row = idx >> 3, cu = (idx & 7) * 8;                             \
            cpasync16(st + (uint32_t)((0 * A_TILE + row * APAD + cu) * 2),      \
                      &Kh_g[row * DKk + cu]);                                   \
            cpasync16(st + (uint32_t)((1 * A_TILE + row * APAD + cu) * 2),      \
                      &Kl_g[row * DKk + cu]);                                   \
            cpasync16(st + (uint32_t)((2 * A_TILE + row * APAD + cu) * 2),      \
                      &Vh_g[(size_t)row * Ss + cu]);                            \
            cpasync16(st + (uint32_t)((3 * A_TILE + row * APAD + cu) * 2),      \
                      &Vl_g[(size_t)row * Ss + cu]);                            \
        }                                                                       \
        CP_COMMIT();                                                            \
    } while (0)

    // ---- load Q tile (64x64 hi/lo) + prefetch KV tile 0 ----
    {
        const __nv_bfloat16* Qh_g = Qhi + baseQK + (size_t)iq * 64 * DKk;
        const __nv_bfloat16* Ql_g = Qlo + baseQK + (size_t)iq * 64 * DKk;
        #pragma unroll
        for (int t = 0; t < 4; t++) {
            int idx = tid + t * 128;
            int row = idx >> 3, cu = (idx & 7) * 8;
            *(uint4*)&smA[0 * A_TILE + row * APAD + cu] = *(const uint4*)&Qh_g[row * DKk + cu];
            *(uint4*)&smA[1 * A_TILE + row * APAD + cu] = *(const uint4*)&Ql_g[row * DKk + cu];
        }
    }
    ISSUE_KV(0, 0);
    __syncthreads();

    const uint32_t a_off = (uint32_t)(((w * 16 + (lane & 15)) * APAD + (lane >> 4) * 8) * 2);
    const uint32_t b_off = (uint32_t)((((lane & 15)) * APAD + (lane >> 4) * 8) * 2);

    uint32_t qh[4][4], ql[4][4];
    #pragma unroll
    for (int kk = 0; kk < 4; kk++) {
        ldsm4(sb + 0 * A_TILE * 2 + a_off + kk * 32, qh[kk][0], qh[kk][1], qh[kk][2], qh[kk][3]);
        ldsm4(sb + 1 * A_TILE * 2 + a_off + kk * 32, ql[kk][0], ql[kk][1], ql[kk][2], ql[kk][3]);
    }

    float o[8][4];
    #pragma unroll
    for (int i = 0; i < 8; i++)
        #pragma unroll
        for (int r = 0; r < 4; r++) o[i][r] = 0.f;
    float m_lo = -1e30f, m_hi = -1e30f, l_lo = 0.f, l_hi = 0.f;

    for (int j = 0; j <= iq; j++) {
        CP_WAIT0();
        __syncthreads();
        if (j < iq) ISSUE_KV(j + 1, (j + 1) & 1);

        const uint32_t stb = sb + (uint32_t)((2 * A_TILE + (j & 1) * STAGE_H) * 2);

        // ---- scores S = Q K^T (3-term) ----
        float s[8][4];
        #pragma unroll
        for (int i = 0; i < 8; i++)
            #pragma unroll
            for (int r = 0; r < 4; r++) s[i][r] = 0.f;

        #pragma unroll
        for (int kk = 0; kk < 4; kk++) {
            uint32_t kh[8][2], kl[8][2];
            #pragma unroll
            for (int np = 0; np < 4; np++) {
                uint32_t t0, t1, t2, t3;
                ldsm4(stb + 0 * A_TILE * 2 + b_off + np * (16 * APAD * 2) + kk * 32, t0, t1, t2, t3);
                kh[2 * np][0] = t0; kh[2 * np][1] = t2;
                kh[2 * np + 1][0] = t1; kh[2 * np + 1][1] = t3;
                ldsm4(stb + 1 * A_TILE * 2 + b_off + np * (16 * APAD * 2) + kk * 32, t0, t1, t2, t3);
                kl[2 * np][0] = t0; kl[2 * np][1] = t2;
                kl[2 * np + 1][0] = t1; kl[2 * np + 1][1] = t3;
            }
            #pragma unroll
            for (int ni = 0; ni < 8; ni++)
                mma16816(s[ni], qh[kk][0], qh[kk][1], qh[kk][2], qh[kk][3],
                         kh[ni][0], kh[ni][1]);
            #pragma unroll
            for (int ni = 0; ni < 8; ni++)
                mma16816(s[ni], qh[kk][0], qh[kk][1], qh[kk][2], qh[kk][3],
                         kl[ni][0], kl[ni][1]);
            #pragma unroll
            for (int ni = 0; ni < 8; ni++)
                mma16816(s[ni], ql[kk][0], ql[kk][1], ql[kk][2], ql[kk][3],
                         kh[ni][0], kh[ni][1]);
        }

        // ---- scale into exp2 domain + causal mask (diagonal tile only) ----
        #pragma unroll
        for (int ni = 0; ni < 8; ni++)
            #pragma unroll
            for (int r = 0; r < 4; r++) s[ni][r] *= SCL2;
        if (j == iq) {
            const int rlo = w * 16 + (lane >> 2), rhi = rlo + 8;
            #pragma unroll
            for (int ni = 0; ni < 8; ni++) {
                const int c0 = ni * 8 + (lane & 3) * 2;
                if (c0 > rlo)     s[ni][0] = -1e30f;
                if (c0 + 1 > rlo) s[ni][1] = -1e30f;
                if (c0 > rhi)     s[ni][2] = -1e30f;
                if (c0 + 1 > rhi) s[ni][3] = -1e30f;
            }
        }

        // ---- softmax part 1: max reduce + o rescale ----
        float mx_lo = s[0][0], mx_hi = s[0][2];
        #pragma unroll
        for (int ni = 0; ni < 8; ni++) {
            mx_lo = fmaxf(mx_lo, fmaxf(s[ni][0], s[ni][1]));
            mx_hi = fmaxf(mx_hi, fmaxf(s[ni][2], s[ni][3]));
        }
        mx_lo = fmaxf(mx_lo, __shfl_xor_sync(0xffffffffu, mx_lo, 1));
        mx_lo = fmaxf(mx_lo, __shfl_xor_sync(0xffffffffu, mx_lo, 2));
        mx_hi = fmaxf(mx_hi, __shfl_xor_sync(0xffffffffu, mx_hi, 1));
        mx_hi = fmaxf(mx_hi, __shfl_xor_sync(0xffffffffu, mx_hi, 2));
        const float mn_lo = fmaxf(m_lo, mx_lo), mn_hi = fmaxf(m_hi, mx_hi);
        const float al_lo = ex2f(m_lo - mn_lo), al_hi = ex2f(m_hi - mn_hi);
        #pragma unroll
        for (int ni = 0; ni < 8; ni++) {
            o[ni][0] *= al_lo; o[ni][1] *= al_lo;
            o[ni][2] *= al_hi; o[ni][3] *= al_hi;
        }

        // ---- PV with fused exp/pack (P blocks produced just-in-time) ----
        float sum_lo = 0.f, sum_hi = 0.f;
        #pragma unroll
        for (int kk = 0; kk < 4; kk++) {
            uint32_t pa[2][2], qa[2][2];
            #pragma unroll
            for (int t = 0; t < 2; t++) {
                const int ni = 2 * kk + t;
                float p0 = ex2f(s[ni][0] - mn_lo);
                float p1 = ex2f(s[ni][1] - mn_lo);
                float p2 = ex2f(s[ni][2] - mn_hi);
                float p3 = ex2f(s[ni][3] - mn_hi);
                sum_lo += p0 + p1; sum_hi += p2 + p3;
                uint32_t h01 = packbf(p0, p1), h23 = packbf(p2, p3);
                pa[t][0] = h01; pa[t][1] = h23;
                qa[t][0] = packbf(p0 - bflo_f(h01), p1 - bfhi_f(h01));
                qa[t][1] = packbf(p2 - bflo_f(h23), p3 - bfhi_f(h23));
            }
            uint32_t vh[8][2], vl[8][2];
            #pragma unroll
            for (int np = 0; np < 4; np++) {
                uint32_t t0, t1, t2, t3;
                ldsm4(stb + 2 * A_TILE * 2 + b_off + np * (16 * APAD * 2) + kk * 32, t0, t1, t2, t3);
                vh[2 * np][0] = t0; vh[2 * np][1] = t2;
                vh[2 * np + 1][0] = t1; vh[2 * np + 1][1] = t3;
                ldsm4(stb + 3 * A_TILE * 2 + b_off + np * (16 * APAD * 2) + kk * 32, t0, t1, t2, t3);
                vl[2 * np][0] = t0; vl[2 * np][1] = t2;
                vl[2 * np + 1][0] = t1; vl[2 * np + 1][1] = t3;
            }
            #pragma unroll
            for (int ni = 0; ni < 8; ni++)
                mma16816(o[ni], pa[0][0], pa[0][1], pa[1][0], pa[1][1],
                         vh[ni][0], vh[ni][1]);
            #pragma unroll
            for (int ni = 0; ni < 8; ni++)
                mma16816(o[ni], pa[0][0], pa[0][1], pa[1][0], pa[1][1],
                         vl[ni][0], vl[ni][1]);
            #pragma unroll
            for (int ni = 0; ni < 8; ni++)
                mma16816(o[ni], qa[0][0], qa[0][1], qa[1][0], qa[1][1],
                         vh[ni][0], vh[ni][1]);
        }

        // ---- softmax part 2: deferred sum reduce + l update ----
        sum_lo += __shfl_xor_sync(0xffffffffu, sum_lo, 1);
        sum_lo += __shfl_xor_sync(0xffffffffu, sum_lo, 2);
        sum_hi += __shfl_xor_sync(0xffffffffu, sum_hi, 1);
        sum_hi += __shfl_xor_sync(0xffffffffu, sum_hi, 2);
        l_lo = l_lo * al_lo + sum_lo;  m_lo = mn_lo;
        l_hi = l_hi * al_hi + sum_hi;  m_hi = mn_hi;
    }

    // ---- epilogue: X[b, s, h*64+dk] as bf16 hi/lo ----
    const float inv_lo = 1.f / l_lo, inv_hi = 1.f / l_hi;
    const int b = bh >> 4, h = bh & 15;
    const int s_lo = iq * 64 + w * 16 + (lane >> 2);
    const int s_hi = s_lo + 8;
    #pragma unroll
    for (int ni = 0; ni < 8; ni++) {
        const int dk = ni * 8 + (lane & 3) * 2;
        const size_t o_lo = ((size_t)(b * Ss + s_lo)) * Dd + h * DKk + dk;
        const size_t o_hi = ((size_t)(b * Ss + s_hi)) * Dd + h * DKk + dk;
        float v0 = o[ni][0] * inv_lo, v1 = o[ni][1] * inv_lo;
        float v2 = o[ni][2] * inv_hi, v3 = o[ni][3] * inv_hi;
        uint32_t hp0 = packbf(v0, v1), hp1 = packbf(v2, v3);
        *(uint32_t*)&Xhi[o_lo] = hp0;
        *(uint32_t*)&Xhi[o_hi] = hp1;
        *(uint32_t*)&Xlo[o_lo] = packbf(v0 - bflo_f(hp0), v1 - bfhi_f(hp0));
        *(uint32_t*)&Xlo[o_hi] = packbf(v2 - bflo_f(hp1), v3 - bfhi_f(hp1));
    }
    #undef ISSUE_KV
}

// ---------------------------------------------------------------------------
extern "C" void kernel_launch(void* const* d_in, const int* in_sizes, int n_in,
                              void* d_out, int out_size)
{
    const float* q   = (const float*)d_in[0];
    const float* k   = (const float*)d_in[1];
    const float* v   = (const float*)d_in[2];
    // d_in[3] = causal mask (int32) — causality computed analytically
    const float* w_q = (const float*)d_in[4];
    const float* b_q = (const float*)d_in[5];
    const float* w_k = (const float*)d_in[6];
    const float* b_k = (const float*)d_in[7];
    const float* w_v = (const float*)d_in[8];
    const float* b_v = (const float*)d_in[9];
    const float* w_o = (const float*)d_in[10];
    const float* b_o = (const float*)d_in[11];
    float* out = (float*)d_out;

    __nv_bfloat16 *pQh, *pQl, *pKh, *pKl, *pVh, *pVl, *pXh, *pXl;
    cudaGetSymbolAddress((void**)&pQh, g_Qhi);
    cudaGetSymbolAddress((void**)&pQl, g_Qlo);
    cudaGetSymbolAddress((void**)&pKh, g_Khi);
    cudaGetSymbolAddress((void**)&pKl, g_Klo);
    cudaGetSymbolAddress((void**)&pVh, g_Vthi);
    cudaGetSymbolAddress((void**)&pVl, g_Vtlo);
    cudaGetSymbolAddress((void**)&pXh, g_Xhi);
    cudaGetSymbolAddress((void**)&pXl, g_Xlo);

    cudaFuncSetAttribute(hgemm_qkv,
                         cudaFuncAttributeMaxDynamicSharedMemorySize, GSMEM);
    cudaFuncSetAttribute(hgemm_out,
                         cudaFuncAttributeMaxDynamicSharedMemorySize, GSMEM);
    cudaFuncSetAttribute(attn_mma_kernel,
                         cudaFuncAttributeMaxDynamicSharedMemorySize, ATTN_SMEM);

    // conversions (weights + activations)
    dim3 wt_grid(32, 32, 4), wt_block(32, 8);
    conv_wt_all<<<wt_grid, wt_block>>>(w_q, w_k, w_v, w_o);
    dim3 ca_grid(4096, 3);
    conv_act_all<<<ca_grid, 256>>>(q, k, v);

    // batched QKV projections (128x128 tiles, 2 CTAs/SM)
    dim3 gemm_grid(Dd / 128, Mm / 128, 3);             // (8, 32, 3)
    hgemm_qkv<<<gemm_grid, 256, GSMEM>>>(b_q, b_k, b_v);

    // attention
    dim3 agrid(Ss / 64, Bb * Hh);                      // (32, 32)
    attn_mma_kernel<<<agrid, 128, ATTN_SMEM>>>(pQh, pQl, pKh, pKl, pVh, pVl, pXh, pXl);

    // output projection
    dim3 gemm_grid1(Dd / 128, Mm / 128, 1);            // (8, 32)
    hgemm_out<<<gemm_grid1, 256, GSMEM>>>(b_o, out);
}

// round 11
// speedup vs baseline: 1.3654x; 1.0269x over previous
#include <cuda_runtime.h>
#include <cuda_bf16.h>
#include <cstdint>

#define Bb  2
#define Ss  2048
#define Dd  1024
#define Hh  16
#define DKk 64
#define Mm  (Bb*Ss)

// ---------------- scratch (allocation-free: device globals) ----------------
__device__ __nv_bfloat16 g_A0hi[(size_t)Mm*Dd], g_A0lo[(size_t)Mm*Dd];
__device__ __nv_bfloat16 g_A1hi[(size_t)Mm*Dd], g_A1lo[(size_t)Mm*Dd];
__device__ __nv_bfloat16 g_A2hi[(size_t)Mm*Dd], g_A2lo[(size_t)Mm*Dd];
__device__ __nv_bfloat16 g_W0hi[(size_t)Dd*Dd], g_W0lo[(size_t)Dd*Dd];
__device__ __nv_bfloat16 g_W1hi[(size_t)Dd*Dd], g_W1lo[(size_t)Dd*Dd];
__device__ __nv_bfloat16 g_W2hi[(size_t)Dd*Dd], g_W2lo[(size_t)Dd*Dd];
__device__ __nv_bfloat16 g_W3hi[(size_t)Dd*Dd], g_W3lo[(size_t)Dd*Dd];
__device__ __nv_bfloat16 g_Qhi[(size_t)Bb*Hh*Ss*DKk], g_Qlo[(size_t)Bb*Hh*Ss*DKk];
__device__ __nv_bfloat16 g_Khi[(size_t)Bb*Hh*Ss*DKk], g_Klo[(size_t)Bb*Hh*Ss*DKk];
__device__ __nv_bfloat16 g_Vthi[(size_t)Bb*Hh*DKk*Ss], g_Vtlo[(size_t)Bb*Hh*DKk*Ss];
__device__ __nv_bfloat16 g_Xhi[(size_t)Mm*Dd], g_Xlo[(size_t)Mm*Dd];

// ---------------- helpers (arch-portable PTX) --------
__device__ __forceinline__ uint32_t smem_u32(const void* p) {
    uint32_t a;
    asm("{ .reg .u64 t; cvta.to.shared.u64 t, %1; cvt.u32.u64 %0, t; }"
        : "=r"(a) : "l"(p));
    return a;
}
__device__ __forceinline__ void ldsm4(uint32_t a, uint32_t& r0, uint32_t& r1,
                                      uint32_t& r2, uint32_t& r3) {
    asm volatile("ldmatrix.sync.aligned.m8n8.x4.shared.b16 {%0,%1,%2,%3}, [%4];"
                 : "=r"(r0), "=r"(r1), "=r"(r2), "=r"(r3) : "r"(a));
}
__device__ __forceinline__ void mma16816(float* c, uint32_t a0, uint32_t a1,
                                         uint32_t a2, uint32_t a3,
                                         uint32_t b0, uint32_t b1) {
    asm volatile(
        "mma.sync.aligned.m16n8k16.row.col.f32.bf16.bf16.f32 "
        "{%0,%1,%2,%3}, {%4,%5,%6,%7}, {%8,%9}, {%0,%1,%2,%3};"
        : "+f"(c[0]), "+f"(c[1]), "+f"(c[2]), "+f"(c[3])
        : "r"(a0), "r"(a1), "r"(a2), "r"(a3), "r"(b0), "r"(b1));
}
__device__ __forceinline__ uint32_t packbf(float lo, float hi) {
    uint32_t r;
    asm("cvt.rn.bf16x2.f32 %0, %1, %2;" : "=r"(r) : "f"(hi), "f"(lo));
    return r;
}
__device__ __forceinline__ float bflo_f(uint32_t p) { return __uint_as_float(p << 16); }
__device__ __forceinline__ float bfhi_f(uint32_t p) { return __uint_as_float(p & 0xffff0000u); }
__device__ __forceinline__ float ex2f(float x) {
    float r;
    asm("ex2.approx.f32 %0, %1;" : "=f"(r) : "f"(x));
    return r;
}

__device__ __forceinline__ void cpasync16(uint32_t saddr, const void* g) {
    asm volatile("cp.async.ca.shared.global [%0], [%1], 16;"
                 :: "r"(saddr), "l"(g) : "memory");
}
#define CP_COMMIT() asm volatile("cp.async.commit_group;" ::: "memory")
#define CP_WAIT0()  asm volatile("cp.async.wait_group 0;" ::: "memory")

// ---------------------------------------------------------------------------
// merged fp32 -> bf16 hi/lo splits for q,k,v activations
// ---------------------------------------------------------------------------
__global__ __launch_bounds__(256) void conv_act_all(
    const float* __restrict__ q, const float* __restrict__ k,
    const float* __restrict__ v)
{
    const float* src = (blockIdx.y == 0) ? q : (blockIdx.y == 1) ? k : v;
    __nv_bfloat16* hi = (blockIdx.y == 0) ? g_A0hi : (blockIdx.y == 1) ? g_A1hi : g_A2hi;
    __nv_bfloat16* lo = (blockIdx.y == 0) ? g_A0lo : (blockIdx.y == 1) ? g_A1lo : g_A2lo;
    int i = blockIdx.x * blockDim.x + threadIdx.x;
    float4 vv = ((const float4*)src)[i];
    uint32_t h0 = packbf(vv.x, vv.y), h1 = packbf(vv.z, vv.w);
    ((uint32_t*)hi)[i * 2 + 0] = h0;
    ((uint32_t*)hi)[i * 2 + 1] = h1;
    ((uint32_t*)lo)[i * 2 + 0] = packbf(vv.x - bflo_f(h0), vv.y - bfhi_f(h0));
    ((uint32_t*)lo)[i * 2 + 1] = packbf(vv.z - bflo_f(h1), vv.w - bfhi_f(h1));
}

// ---------------------------------------------------------------------------
// merged weight transpose + split: W[K,N] -> WT[N,K] hi/lo, 4 weights
// ---------------------------------------------------------------------------
__global__ __launch_bounds__(256) void conv_wt_all(
    const float* __restrict__ w0, const float* __restrict__ w1,
    const float* __restrict__ w2, const float* __restrict__ w3)
{
    __shared__ float ts[32][33];
    const int z = blockIdx.z;
    const float* W = (z == 0) ? w0 : (z == 1) ? w1 : (z == 2) ? w2 : w3;
    __nv_bfloat16* hiT = (z == 0) ? g_W0hi : (z == 1) ? g_W1hi : (z == 2) ? g_W2hi : g_W3hi;
    __nv_bfloat16* loT = (z == 0) ? g_W0lo : (z == 1) ? g_W1lo : (z == 2) ? g_W2lo : g_W3lo;
    int tx = threadIdx.x, ty = threadIdx.y;          // 32 x 8
    int bn = blockIdx.x * 32, bk = blockIdx.y * 32;
    #pragma unroll
    for (int r = 0; r < 4; r++)
        ts[ty + r * 8][tx] = W[(size_t)(bk + ty + r * 8) * Dd + bn + tx];
    __syncthreads();
    #pragma unroll
    for (int r = 0; r < 4; r++) {
        float x = ts[tx][ty + r * 8];
        __nv_bfloat16 h = __float2bfloat16(x);
        size_t o = (size_t)(bn + ty + r * 8) * Dd + bk + tx;
        hiT[o] = h;
        loT[o] = __float2bfloat16(x - __bfloat162float(h));
    }
}

// ---------------------------------------------------------------------------
// HMMA bf16x3 GEMM body: cp.async double-buffered, 2 CTAs/SM.
// CTA 128x128, K-chunk 32, 8 warps (2m x 4n), warp tile 64x32.
// Fragment reuse across the 3 passes: 12 ldsm4/ks instead of 18.
// mode 0: fp32 row-major; 1: bf16 hi/lo [B,H,S,DK]; 2: bf16 hi/lo [B,H,DK,S].
// ---------------------------------------------------------------------------
#define KCH   32
#define NCHUNK (Dd / KCH)          // 32
#define SROW  40                   // padded halves per row
#define ABYTES (128 * SROW * 2)    // 10240 B per array
#define BUFB  (4 * ABYTES)         // 40960 B per stage
#define GSMEM (2 * BUFB)           // 81920 B

__device__ __forceinline__ void hgemm_body(
    const __nv_bfloat16* __restrict__ Ahi, const __nv_bfloat16* __restrict__ Alo,
    const __nv_bfloat16* __restrict__ Whi, const __nv_bfloat16* __restrict__ Wlo,
    const float* __restrict__ bias, float* __restrict__ Cf,
    __nv_bfloat16* __restrict__ Chi, __nv_bfloat16* __restrict__ Clo,
    int mode, __nv_bfloat16* sm)
{
    const int tid  = threadIdx.x;
    const int wid  = tid >> 5, lane = tid & 31;
    const int bm   = blockIdx.y * 128, bn = blockIdx.x * 128;
    const int wm   = wid & 1, wn = wid >> 1;

    float c[4][4][4];
    #pragma unroll
    for (int i = 0; i < 4; i++)
        #pragma unroll
        for (int j = 0; j < 4; j++)
            #pragma unroll
            for (int r = 0; r < 4; r++) c[i][j][r] = 0.f;

    const int r0 = tid >> 2,         q0 = (tid & 3) * 8;
    const int r1 = (tid + 256) >> 2, q1 = ((tid + 256) & 3) * 8;
    const uint32_t sb = smem_u32(sm);

    #define ISSUE_CHUNK(cc, base) do {                                          \
        const int k0_ = (cc) * KCH;                                             \
        cpasync16((base) + (uint32_t)((0 * 128 * SROW + r0 * SROW + q0) * 2),   \
                  &Ahi[(size_t)(bm + r0) * Dd + k0_ + q0]);                     \
        cpasync16((base) + (uint32_t)((0 * 128 * SROW + r1 * SROW + q1) * 2),   \
                  &Ahi[(size_t)(bm + r1) * Dd + k0_ + q1]);                     \
        cpasync16((base) + (uint32_t)((1 * 128 * SROW + r0 * SROW + q0) * 2),   \
                  &Alo[(size_t)(bm + r0) * Dd + k0_ + q0]);                     \
        cpasync16((base) + (uint32_t)((1 * 128 * SROW + r1 * SROW + q1) * 2),   \
                  &Alo[(size_t)(bm + r1) * Dd + k0_ + q1]);                     \
        cpasync16((base) + (uint32_t)((2 * 128 * SROW + r0 * SROW + q0) * 2),   \
                  &Whi[(size_t)(bn + r0) * Dd + k0_ + q0]);                     \
        cpasync16((base) + (uint32_t)((2 * 128 * SROW + r1 * SROW + q1) * 2),   \
                  &Whi[(size_t)(bn + r1) * Dd + k0_ + q1]);                     \
        cpasync16((base) + (uint32_t)((3 * 128 * SROW + r0 * SROW + q0) * 2),   \
                  &Wlo[(size_t)(bn + r0) * Dd + k0_ + q0]);                     \
        cpasync16((base) + (uint32_t)((3 * 128 * SROW + r1 * SROW + q1) * 2),   \
                  &Wlo[(size_t)(bn + r1) * Dd + k0_ + q1]);                     \
        CP_COMMIT();                                                            \
    } while (0)

    const uint32_t aoff =
        (uint32_t)(((wm * 64 + (lane & 15)) * SROW + (lane >> 4) * 8) * 2);
    // B ldsm4: lanes 0-7 -> (n0,k0), 8-15 -> (n0,k8), 16-23 -> (n1,k0), 24-31 -> (n1,k8)
    const uint32_t boff4 =
        (uint32_t)(((wn * 32 + (lane >> 4) * 8 + (lane & 7)) * SROW
                    + ((lane >> 3) & 1) * 8) * 2);

    ISSUE_CHUNK(0, sb);

    for (int cc = 0; cc < NCHUNK; cc++) {
        CP_WAIT0();
        __syncthreads();
        if (cc + 1 < NCHUNK)
            ISSUE_CHUNK(cc + 1, sb + (uint32_t)((cc + 1) & 1) * BUFB);

        const uint32_t bufb = sb + (uint32_t)(cc & 1) * BUFB;
        #pragma unroll
        for (int ks = 0; ks < 2; ks++) {
            uint32_t ah[4][4], bh[4][2], bl[4][2];
            // A-hi fragments
            #pragma unroll
            for (int mi = 0; mi < 4; mi++)
                ldsm4(bufb + aoff + mi * (16 * SROW * 2) + ks * 32,
                      ah[mi][0], ah[mi][1], ah[mi][2], ah[mi][3]);
            // B-hi and B-lo fragments
            #pragma unroll
            for (int nb = 0; nb < 2; nb++)
                ldsm4(bufb + 2u * ABYTES + boff4 + nb * (16 * SROW * 2) + ks * 32,
                      bh[2 * nb][0], bh[2 * nb][1], bh[2 * nb + 1][0], bh[2 * nb + 1][1]);
            #pragma unroll
            for (int nb = 0; nb < 2; nb++)
                ldsm4(bufb + 3u * ABYTES + boff4 + nb * (16 * SROW * 2) + ks * 32,
                      bl[2 * nb][0], bl[2 * nb][1], bl[2 * nb + 1][0], bl[2 * nb + 1][1]);
            // pass 0: Ah * Bh
            #pragma unroll
            for (int mi = 0; mi < 4; mi++)
                #pragma unroll
                for (int ni = 0; ni < 4; ni++)
                    mma16816(c[mi][ni], ah[mi][0], ah[mi][1], ah[mi][2], ah[mi][3],
                             bh[ni][0], bh[ni][1]);
            // pass 1: Ah * Bl (A fragments reused)
            #pragma unroll
            for (int mi = 0; mi < 4; mi++)
                #pragma unroll
                for (int ni = 0; ni < 4; ni++)
                    mma16816(c[mi][ni], ah[mi][0], ah[mi][1], ah[mi][2], ah[mi][3],
                             bl[ni][0], bl[ni][1]);
            // A-lo fragments (overwrite ah)
            #pragma unroll
            for (int mi = 0; mi < 4; mi++)
                ldsm4(bufb + (uint32_t)ABYTES + aoff + mi * (16 * SROW * 2) + ks * 32,
                      ah[mi][0], ah[mi][1], ah[mi][2], ah[mi][3]);
            // pass 2: Al * Bh (B-hi fragments reused)
            #pragma unroll
            for (int mi = 0; mi < 4; mi++)
                #pragma unroll
                for (int ni = 0; ni < 4; ni++)
                    mma16816(c[mi][ni], ah[mi][0], ah[mi][1], ah[mi][2], ah[mi][3],
                             bh[ni][0], bh[ni][1]);
        }
    }

    // ---- epilogue ----
    const int mrow0 = bm + wm * 64 + (lane >> 2);
    const int ncol0 = bn + wn * 32 + (lane & 3) * 2;
    #pragma unroll
    for (int mi = 0; mi < 4; mi++) {
        #pragma unroll
        for (int h2 = 0; h2 < 2; h2++) {
            const int m = mrow0 + mi * 16 + h2 * 8;
            const int b = m >> 11, s = m & 2047;
            #pragma unroll
            for (int ni = 0; ni < 4; ni++) {
                const int n = ncol0 + ni * 8;
                float v0 = c[mi][ni][h2 * 2 + 0] + bias[n];
                float v1 = c[mi][ni][h2 * 2 + 1] + bias[n + 1];
                if (mode == 0) {
                    float2 v; v.x = v0; v.y = v1;
                    *(float2*)&Cf[(size_t)m * Dd + n] = v;
                } else {
                    const int h = n >> 6, dk = n & 63;
                    uint32_t hp = packbf(v0, v1);
                    uint32_t lp = packbf(v0 - bflo_f(hp), v1 - bfhi_f(hp));
                    if (mode == 1) {
                        size_t o = (((size_t)(b * Hh + h)) * Ss + s) * DKk + dk;
                        *(uint32_t*)&Chi[o] = hp;
                        *(uint32_t*)&Clo[o] = lp;
                    } else {
                        size_t o = (((size_t)(b * Hh + h)) * DKk + dk) * Ss + s;
                        Chi[o]      = __ushort_as_bfloat16((uint16_t)(hp & 0xffff));
                        Chi[o + Ss] = __ushort_as_bfloat16((uint16_t)(hp >> 16));
                        Clo[o]      = __ushort_as_bfloat16((uint16_t)(lp & 0xffff));
                        Clo[o + Ss] = __ushort_as_bfloat16((uint16_t)(lp >> 16));
                    }
                }
            }
        }
    }
    #undef ISSUE_CHUNK
}

// batched QKV projections: blockIdx.z selects {Q, K, V}
__global__ __launch_bounds__(256, 2) void hgemm_qkv(
    const float* __restrict__ b_q, const float* __restrict__ b_k,
    const float* __restrict__ b_v)
{
    extern __shared__ __nv_bfloat16 smg[];
    const int z = blockIdx.z;
    if (z == 0)
        hgemm_body(g_A0hi, g_A0lo, g_W0hi, g_W0lo, b_q, nullptr, g_Qhi, g_Qlo, 1, smg);
    else if (z == 1)
        hgemm_body(g_A1hi, g_A1lo, g_W1hi, g_W1lo, b_k, nullptr, g_Khi, g_Klo, 1, smg);
    else
        hgemm_body(g_A2hi, g_A2lo, g_W2hi, g_W2lo, b_v, nullptr, g_Vthi, g_Vtlo, 2, smg);
}

__global__ __launch_bounds__(256, 2) void hgemm_out(
    const float* __restrict__ b_o, float* __restrict__ out)
{
    extern __shared__ __nv_bfloat16 smg[];
    hgemm_body(g_Xhi, g_Xlo, g_W3hi, g_W3lo, b_o, out, nullptr, nullptr, 0, smg);
}

// ---------------------------------------------------------------------------
// HMMA flash attention, bf16x3, causal, cp.async double-buffered KV.
// CTA: 64 query rows of one (b,h); 4 warps x 16 rows. KV tiles of 64 keys.
// (R7/R8 form — best measured variant)
// ---------------------------------------------------------------------------
#define APAD 72
#define A_TILE (64 * APAD)             // 4608 halves = 9216 B
#define STAGE_H (4 * A_TILE)           // KH,KL,VH,VL per stage
#define ATTN_SMEM ((2 * A_TILE + 2 * STAGE_H) * 2)   // 92160 B
#define SCL2 0.18033688f               // 0.125 * log2(e)

__global__ __launch_bounds__(128, 1) void attn_mma_kernel(
    const __nv_bfloat16* __restrict__ Qhi, const __nv_bfloat16* __restrict__ Qlo,
    const __nv_bfloat16* __restrict__ Khi, const __nv_bfloat16* __restrict__ Klo,
    const __nv_bfloat16* __restrict__ Vthi, const __nv_bfloat16* __restrict__ Vtlo,
    __nv_bfloat16* __restrict__ Xhi, __nv_bfloat16* __restrict__ Xlo)
{
    extern __shared__ __nv_bfloat16 smA[];
    const int tid  = threadIdx.x;
    const int w    = tid >> 5, lane = tid & 31;
    const int bh   = blockIdx.y;
    const int iq   = gridDim.x - 1 - blockIdx.x;   // long CTAs first
    const size_t baseQK = (size_t)bh * Ss * DKk;
    const size_t baseV  = (size_t)bh * DKk * Ss;
    const uint32_t sb = smem_u32(smA);

    #define ISSUE_KV(j, stg) do {                                               \
        const __nv_bfloat16* Kh_g = Khi + baseQK + (size_t)(j) * 64 * DKk;      \
        const __nv_bfloat16* Kl_g = Klo + baseQK + (size_t)(j) * 64 * DKk;      \
        const __nv_bfloat16* Vh_g = Vthi + baseV + (size_t)(j) * 64;            \
        const __nv_bfloat16* Vl_g = Vtlo + baseV + (size_t)(j) * 64;            \
        const uint32_t st = sb + (uint32_t)((2 * A_TILE + (stg) * STAGE_H) * 2);\
        _Pragma("unroll")                                                       \
        for (int t = 0; t < 4; t++) {                                           \
            int idx = tid + t * 128;                                            \
            int row = idx >> 3, cu = (idx & 7) * 8;                             \
            cpasync16(st + (uint32_t)((0 * A_TILE + row * APAD + cu) * 2),      \
                      &Kh_g[row * DKk + cu]);                                   \
            cpasync16(st + (uint32_t)((1 * A_TILE + row * APAD + cu) * 2),      \
                      &Kl_g[row * DKk + cu]);                                   \
            cpasync16(st + (uint32_t)((2 * A_TILE + row * APAD + cu) * 2),      \
                      &Vh_g[(size_t)row * Ss + cu]);                            \
            cpasync16(st + (uint32_t)((3 * A_TILE + row * APAD + cu) * 2),      \
                      &Vl_g[(size_t)row * Ss + cu]);                            \
        }                                                                       \
        CP_COMMIT();                                                            \
    } while (0)

    // ---- load Q tile (64x64 hi/lo) + prefetch KV tile 0 ----
    {
        const __nv_bfloat16* Qh_g = Qhi + baseQK + (size_t)iq * 64 * DKk;
        const __nv_bfloat16* Ql_g = Qlo + baseQK + (size_t)iq * 64 * DKk;
        #pragma unroll
        for (int t = 0; t < 4; t++) {
            int idx = tid + t * 128;
            int row = idx >> 3, cu = (idx & 7) * 8;
            *(uint4*)&smA[0 * A_TILE + row * APAD + cu] = *(const uint4*)&Qh_g[row * DKk + cu];
            *(uint4*)&smA[1 * A_TILE + row * APAD + cu] = *(const uint4*)&Ql_g[row * DKk + cu];
        }
    }
    ISSUE_KV(0, 0);
    __syncthreads();

    const uint32_t a_off = (uint32_t)(((w * 16 + (lane & 15)) * APAD + (lane >> 4) * 8) * 2);
    const uint32_t b_off = (uint32_t)((((lane & 15)) * APAD + (lane >> 4) * 8) * 2);

    uint32_t qh[4][4], ql[4][4];
    #pragma unroll
    for (int kk = 0; kk < 4; kk++) {
        ldsm4(sb + 0 * A_TILE * 2 + a_off + kk * 32, qh[kk][0], qh[kk][1], qh[kk][2], qh[kk][3]);
        ldsm4(sb + 1 * A_TILE * 2 + a_off + kk * 32, ql[kk][0], ql[kk][1], ql[kk][2], ql[kk][3]);
    }

    float o[8][4];
    #pragma unroll
    for (int i = 0; i < 8; i++)
        #pragma unroll
        for (int r = 0; r < 4; r++) o[i][r] = 0.f;
    float m_lo = -1e30f, m_hi = -1e30f, l_lo = 0.f, l_hi = 0.f;

    for (int j = 0; j <= iq; j++) {
        CP_WAIT0();
        __syncthreads();
        if (j < iq) ISSUE_KV(j + 1, (j + 1) & 1);

        const uint32_t stb = sb + (uint32_t)((2 * A_TILE + (j & 1) * STAGE_H) * 2);

        // ---- scores S = Q K^T (3-term) ----
        float s[8][4];
        #pragma unroll
        for (int i = 0; i < 8; i++)
            #pragma unroll
            for (int r = 0; r < 4; r++) s[i][r] = 0.f;

        #pragma unroll
        for (int kk = 0; kk < 4; kk++) {
            uint32_t kh[8][2], kl[8][2];
            #pragma unroll
            for (int np = 0; np < 4; np++) {
                uint32_t t0, t1, t2, t3;
                ldsm4(stb + 0 * A_TILE * 2 + b_off + np * (16 * APAD * 2) + kk * 32, t0, t1, t2, t3);
                kh[2 * np][0] = t0; kh[2 * np][1] = t2;
                kh[2 * np + 1][0] = t1; kh[2 * np + 1][1] = t3;
                ldsm4(stb + 1 * A_TILE * 2 + b_off + np * (16 * APAD * 2) + kk * 32, t0, t1, t2, t3);
                kl[2 * np][0] = t0; kl[2 * np][1] = t2;
                kl[2 * np + 1][0] = t1; kl[2 * np + 1][1] = t3;
            }
            #pragma unroll
            for (int ni = 0; ni < 8; ni++)
                mma16816(s[ni], qh[kk][0], qh[kk][1], qh[kk][2], qh[kk][3],
                         kh[ni][0], kh[ni][1]);
            #pragma unroll
            for (int ni = 0; ni < 8; ni++)
                mma16816(s[ni], qh[kk][0], qh[kk][1], qh[kk][2], qh[kk][3],
                         kl[ni][0], kl[ni][1]);
            #pragma unroll
            for (int ni = 0; ni < 8; ni++)
                mma16816(s[ni], ql[kk][0], ql[kk][1], ql[kk][2], ql[kk][3],
                         kh[ni][0], kh[ni][1]);
        }

        // ---- scale into exp2 domain + causal mask (diagonal tile only) ----
        #pragma unroll
        for (int ni = 0; ni < 8; ni++)
            #pragma unroll
            for (int r = 0; r < 4; r++) s[ni][r] *= SCL2;
        if (j == iq) {
            const int rlo = w * 16 + (lane >> 2), rhi = rlo + 8;
            #pragma unroll
            for (int ni = 0; ni < 8; ni++) {
                const int c0 = ni * 8 + (lane & 3) * 2;
                if (c0 > rlo)     s[ni][0] = -1e30f;
                if (c0 + 1 > rlo) s[ni][1] = -1e30f;
                if (c0 > rhi)     s[ni][2] = -1e30f;
                if (c0 + 1 > rhi) s[ni][3] = -1e30f;
            }
        }

        // ---- online softmax (fp32, base-2) ----
        float mx_lo = s[0][0], mx_hi = s[0][2];
        #pragma unroll
        for (int ni = 0; ni < 8; ni++) {
            mx_lo = fmaxf(mx_lo, fmaxf(s[ni][0], s[ni][1]));
            mx_hi = fmaxf(mx_hi, fmaxf(s[ni][2], s[ni][3]));
        }
        mx_lo = fmaxf(mx_lo, __shfl_xor_sync(0xffffffffu, mx_lo, 1));
        mx_lo = fmaxf(mx_lo, __shfl_xor_sync(0xffffffffu, mx_lo, 2));
        mx_hi = fmaxf(mx_hi, __shfl_xor_sync(0xffffffffu, mx_hi, 1));
        mx_hi = fmaxf(mx_hi, __shfl_xor_sync(0xffffffffu, mx_hi, 2));
        const float mn_lo = fmaxf(m_lo, mx_lo), mn_hi = fmaxf(m_hi, mx_hi);
        const float al_lo = ex2f(m_lo - mn_lo), al_hi = ex2f(m_hi - mn_hi);

        uint32_t ph[8][2], pl[8][2];
        float sum_lo = 0.f, sum_hi = 0.f;
        #pragma unroll
        for (int ni = 0; ni < 8; ni++) {
            float p0 = ex2f(s[ni][0] - mn_lo);
            float p1 = ex2f(s[ni][1] - mn_lo);
            float p2 = ex2f(s[ni][2] - mn_hi);
            float p3 = ex2f(s[ni][3] - mn_hi);
            sum_lo += p0 + p1; sum_hi += p2 + p3;
            uint32_t h01 = packbf(p0, p1), h23 = packbf(p2, p3);
            ph[ni][0] = h01; ph[ni][1] = h23;
            pl[ni][0] = packbf(p0 - bflo_f(h01), p1 - bfhi_f(h01));
            pl[ni][1] = packbf(p2 - bflo_f(h23), p3 - bfhi_f(h23));
        }
        sum_lo += __shfl_xor_sync(0xffffffffu, sum_lo, 1);
        sum_lo += __shfl_xor_sync(0xffffffffu, sum_lo, 2);
        sum_hi += __shfl_xor_sync(0xffffffffu, sum_hi, 1);
        sum_hi += __shfl_xor_sync(0xffffffffu, sum_hi, 2);
        l_lo = l_lo * al_lo + sum_lo;  m_lo = mn_lo;
        l_hi = l_hi * al_hi + sum_hi;  m_hi = mn_hi;
        #pragma unroll
        for (int ni = 0; ni < 8; ni++) {
            o[ni][0] *= al_lo; o[ni][1] *= al_lo;
            o[ni][2] *= al_hi; o[ni][3] *= al_hi;
        }

        // ---- O += P V (3-term) ----
        #pragma unroll
        for (int kk = 0; kk < 4; kk++) {
            uint32_t vh[8][2], vl[8][2];
            #pragma unroll
            for (int np = 0; np < 4; np++) {
                uint32_t t0, t1, t2, t3;
                ldsm4(stb + 2 * A_TILE * 2 + b_off + np * (16 * APAD * 2) + kk * 32, t0, t1, t2, t3);
                vh[2 * np][0] = t0; vh[2 * np][1] = t2;
                vh[2 * np + 1][0] = t1; vh[2 * np + 1][1] = t3;
                ldsm4(stb + 3 * A_TILE * 2 + b_off + np * (16 * APAD * 2) + kk * 32, t0, t1, t2, t3);
                vl[2 * np][0] = t0; vl[2 * np][1] = t2;
                vl[2 * np + 1][0] = t1; vl[2 * np + 1][1] = t3;
            }
            const uint32_t pa0 = ph[2 * kk][0], pa1 = ph[2 * kk][1];
            const uint32_t pa2 = ph[2 * kk + 1][0], pa3 = ph[2 * kk + 1][1];
            const uint32_t qa0 = pl[2 * kk][0], qa1 = pl[2 * kk][1];
            const uint32_t qa2 = pl[2 * kk + 1][0], qa3 = pl[2 * kk + 1][1];
            #pragma unroll
            for (int ni = 0; ni < 8; ni++)
                mma16816(o[ni], pa0, pa1, pa2, pa3, vh[ni][0], vh[ni][1]);
            #pragma unroll
            for (int ni = 0; ni < 8; ni++)
                mma16816(o[ni], pa0, pa1, pa2, pa3, vl[ni][0], vl[ni][1]);
            #pragma unroll
            for (int ni = 0; ni < 8; ni++)
                mma16816(o[ni], qa0, qa1, qa2, qa3, vh[ni][0], vh[ni][1]);
        }
    }

    // ---- epilogue: X[b, s, h*64+dk] as bf16 hi/lo ----
    const float inv_lo = 1.f / l_lo, inv_hi = 1.f / l_hi;
    const int b = bh >> 4, h = bh & 15;
    const int s_lo = iq * 64 + w * 16 + (lane >> 2);
    const int s_hi = s_lo + 8;
    #pragma unroll
    for (int ni = 0; ni < 8; ni++) {
        const int dk = ni * 8 + (lane & 3) * 2;
        const size_t o_lo = ((size_t)(b * Ss + s_lo)) * Dd + h * DKk + dk;
        const size_t o_hi = ((size_t)(b * Ss + s_hi)) * Dd + h * DKk + dk;
        float v0 = o[ni][0] * inv_lo, v1 = o[ni][1] * inv_lo;
        float v2 = o[ni][2] * inv_hi, v3 = o[ni][3] * inv_hi;
        uint32_t hp0 = packbf(v0, v1), hp1 = packbf(v2, v3);
        *(uint32_t*)&Xhi[o_lo] = hp0;
        *(uint32_t*)&Xhi[o_hi] = hp1;
        *(uint32_t*)&Xlo[o_lo] = packbf(v0 - bflo_f(hp0), v1 - bfhi_f(hp0));
        *(uint32_t*)&Xlo[o_hi] = packbf(v2 - bflo_f(hp1), v3 - bfhi_f(hp1));
    }
    #undef ISSUE_KV
}

// ---------------------------------------------------------------------------
extern "C" void kernel_launch(void* const* d_in, const int* in_sizes, int n_in,
                              void* d_out, int out_size)
{
    const float* q   = (const float*)d_in[0];
    const float* k   = (const float*)d_in[1];
    const float* v   = (const float*)d_in[2];
    // d_in[3] = causal mask (int32) — causality computed analytically
    const float* w_q = (const float*)d_in[4];
    const float* b_q = (const float*)d_in[5];
    const float* w_k = (const float*)d_in[6];
    const float* b_k = (const float*)d_in[7];
    const float* w_v = (const float*)d_in[8];
    const float* b_v = (const float*)d_in[9];
    const float* w_o = (const float*)d_in[10];
    const float* b_o = (const float*)d_in[11];
    float* out = (float*)d_out;

    __nv_bfloat16 *pQh, *pQl, *pKh, *pKl, *pVh, *pVl, *pXh, *pXl;
    cudaGetSymbolAddress((void**)&pQh, g_Qhi);
    cudaGetSymbolAddress((void**)&pQl, g_Qlo);
    cudaGetSymbolAddress((void**)&pKh, g_Khi);
    cudaGetSymbolAddress((void**)&pKl, g_Klo);
    cudaGetSymbolAddress((void**)&pVh, g_Vthi);
    cudaGetSymbolAddress((void**)&pVl, g_Vtlo);
    cudaGetSymbolAddress((void**)&pXh, g_Xhi);
    cudaGetSymbolAddress((void**)&pXl, g_Xlo);

    cudaFuncSetAttribute(hgemm_qkv,
                         cudaFuncAttributeMaxDynamicSharedMemorySize, GSMEM);
    cudaFuncSetAttribute(hgemm_out,
                         cudaFuncAttributeMaxDynamicSharedMemorySize, GSMEM);
    cudaFuncSetAttribute(attn_mma_kernel,
                         cudaFuncAttributeMaxDynamicSharedMemorySize, ATTN_SMEM);

    // conversions (weights + activations)
    dim3 wt_grid(32, 32, 4), wt_block(32, 8);
    conv_wt_all<<<wt_grid, wt_block>>>(w_q, w_k, w_v, w_o);
    dim3 ca_grid(4096, 3);
    conv_act_all<<<ca_grid, 256>>>(q, k, v);

    // batched QKV projections (128x128 tiles, 2 CTAs/SM)
    dim3 gemm_grid(Dd / 128, Mm / 128, 3);             // (8, 32, 3)
    hgemm_qkv<<<gemm_grid, 256, GSMEM>>>(b_q, b_k, b_v);

    // attention
    dim3 agrid(Ss / 64, Bb * Hh);                      // (32, 32)
    attn_mma_kernel<<<agrid, 128, ATTN_SMEM>>>(pQh, pQl, pKh, pKl, pVh, pVl, pXh, pXl);

    // output projection
    dim3 gemm_grid1(Dd / 128, Mm / 128, 1);            // (8, 32)
    hgemm_out<<<gemm_grid1, 256, GSMEM>>>(b_o, out);
}